// round 1
// baseline (speedup 1.0000x reference)
#include <cuda_runtime.h>

// Problem constants (fixed shapes from setup_inputs)
#define CIN   128
#define HH    32
#define WW    32
#define BATCH 16
#define COUT  256
#define DTOT  1152   // CIN*3*3, = 18*64 exactly (no padding)
#define RCH   18     // chunks
#define NPIX  (BATCH*HH*WW)

// Scratch (no cudaMalloc allowed)
__device__ float    g_wq[DTOT * COUT];   // quantized weight, [d][m]
__device__ int      g_tab[DTOT];         // packed im2col offsets: off | (p<<20)
__device__ unsigned g_kmin, g_kmax;      // monotonic float keys

__device__ __forceinline__ unsigned f2key(float f) {
    unsigned u = __float_as_uint(f);
    return (u & 0x80000000u) ? ~u : (u | 0x80000000u);
}
__device__ __forceinline__ float key2f(unsigned k) {
    unsigned u = (k & 0x80000000u) ? (k ^ 0x80000000u) : ~k;
    return __uint_as_float(u);
}

__global__ void k_init() {
    g_kmin = 0xFFFFFFFFu;
    g_kmax = 0u;
}

// 288 blocks x 256 threads x float4 = 294912 elements exactly
__global__ void k_minmax(const float* __restrict__ w) {
    int idx = (blockIdx.x * 256 + threadIdx.x) * 4;
    float4 v = *(const float4*)(w + idx);
    float lmin = fminf(fminf(v.x, v.y), fminf(v.z, v.w));
    float lmax = fmaxf(fmaxf(v.x, v.y), fmaxf(v.z, v.w));
    unsigned kmin = f2key(lmin), kmax = f2key(lmax);
#pragma unroll
    for (int s = 16; s; s >>= 1) {
        kmin = min(kmin, __shfl_xor_sync(0xffffffffu, kmin, s));
        kmax = max(kmax, __shfl_xor_sync(0xffffffffu, kmax, s));
    }
    __shared__ unsigned smin[8], smax[8];
    int wid = threadIdx.x >> 5;
    if ((threadIdx.x & 31) == 0) { smin[wid] = kmin; smax[wid] = kmax; }
    __syncthreads();
    if (threadIdx.x == 0) {
#pragma unroll
        for (int i = 1; i < 8; i++) {
            kmin = min(kmin, smin[i]);
            kmax = max(kmax, smax[i]);
        }
        atomicMin(&g_kmin, kmin);
        atomicMax(&g_kmax, kmax);
    }
}

// grid = DTOT blocks, 256 threads. Quantize weight[m*DTOT + d] -> g_wq[d*COUT + m].
// jnp: scale = 15/(max-min+1e-9); clip(round(w*scale), -7, 7). jnp.round == rintf.
__global__ void k_quant(const float* __restrict__ w) {
    float wmin = key2f(g_kmin), wmax = key2f(g_kmax);
    float scale = 15.0f / (wmax - wmin + 1e-9f);
    int d = blockIdx.x, m = threadIdx.x;
    float q = rintf(w[m * DTOT + d] * scale);
    q = fminf(fmaxf(q, -7.0f), 7.0f);
    g_wq[d * COUT + m] = q;
    if (m == 0) {
        int c  = d / 9;
        int p  = d - c * 9;
        int di = p / 3;
        int dj = p - di * 3;
        // offset relative to (inb + h*32 + w - 33):  c*1024 + di*32 + dj
        g_tab[d] = (c * 1024 + di * 32 + dj) | (p << 20);
    }
}

// Implicit-GEMM conv with per-chunk (K=64) sign counting.
// Tile: BM=128 pixels x BN=64 out-channels, 256 threads, 8x4 micro-tile.
// grid.x = (NPIX/128) * (COUT/64) = 128*4 = 512
__global__ void __launch_bounds__(256, 2)
k_gemm(const float* __restrict__ inp, float* __restrict__ out) {
    __shared__ float Xs[64][128];  // [k][pixel]
    __shared__ float Ws[64][64];   // [k][m]

    const int tid = threadIdx.x;
    const int bm  = blockIdx.x >> 2;
    const int m0  = (blockIdx.x & 3) * 64;
    const int n0  = bm * 128;
    const int b   = n0 >> 10;        // 1024 pixels per image; tile stays in one image
    const int hw0 = n0 & 1023;
    const float* inb = inp + (size_t)b * (CIN * 1024);

    // ---- Xs loader indices (128 pixels x 2 k-rows per pass) ----
    const int lpix = tid & 127;
    const int lk2  = tid >> 7;
    const int hw   = hw0 + lpix;
    const int h    = hw >> 5;
    const int wc   = hw & 31;
    const float* base = inb + h * 32 + wc - 33;
    // 9-bit validity mask over p = di*3+dj for this pixel's 3x3 halo
    int vmask = 0;
#pragma unroll
    for (int di = 0; di < 3; ++di)
#pragma unroll
        for (int dj = 0; dj < 3; ++dj) {
            int hh = h + di - 1, wwp = wc + dj - 1;
            if (hh >= 0 && hh < 32 && wwp >= 0 && wwp < 32)
                vmask |= 1 << (di * 3 + dj);
        }

    // ---- Ws loader indices (64 m x 4 k-rows per pass) ----
    const int lm  = tid & 63;
    const int lk4 = tid >> 6;

    // ---- compute thread mapping ----
    const int tx = tid & 15, ty = tid >> 4;
    const int i0 = ty * 8;   // pixel offset
    const int j0 = tx * 4;   // channel offset

    float cnt[8][4];
#pragma unroll
    for (int i = 0; i < 8; i++)
#pragma unroll
        for (int j = 0; j < 4; j++) cnt[i][j] = 0.0f;

    for (int r = 0; r < RCH; ++r) {
        // stage X (im2col on the fly)
#pragma unroll
        for (int kk = 0; kk < 32; ++kk) {
            int k   = kk * 2 + lk2;
            int e   = g_tab[r * 64 + k];
            int off = e & 0xFFFFF;
            int p   = e >> 20;
            float v = 0.0f;
            if ((vmask >> p) & 1) v = __ldg(base + off);
            Xs[k][lpix] = v;
        }
        // stage W
#pragma unroll
        for (int kk = 0; kk < 16; ++kk) {
            int k = kk * 4 + lk4;
            Ws[k][lm] = g_wq[(r * 64 + k) * COUT + m0 + lm];
        }
        __syncthreads();

        float acc[8][4];
#pragma unroll
        for (int i = 0; i < 8; i++)
#pragma unroll
            for (int j = 0; j < 4; j++) acc[i][j] = 0.0f;

#pragma unroll 8
        for (int k = 0; k < 64; ++k) {
            float4 xa = *(const float4*)&Xs[k][i0];
            float4 xb = *(const float4*)&Xs[k][i0 + 4];
            float4 wv = *(const float4*)&Ws[k][j0];
            float xr[8] = {xa.x, xa.y, xa.z, xa.w, xb.x, xb.y, xb.z, xb.w};
            float wr[4] = {wv.x, wv.y, wv.z, wv.w};
#pragma unroll
            for (int i = 0; i < 8; i++)
#pragma unroll
                for (int j = 0; j < 4; j++)
                    acc[i][j] = fmaf(xr[i], wr[j], acc[i][j]);
        }

        // threshold (>= 0 -> +1), per chunk
#pragma unroll
        for (int i = 0; i < 8; i++)
#pragma unroll
            for (int j = 0; j < 4; j++)
                cnt[i][j] += (acc[i][j] >= 0.0f) ? 1.0f : 0.0f;

        __syncthreads();
    }

    // store: out[(b*COUT + m)*1024 + hw0 + i0 + i]
#pragma unroll
    for (int j = 0; j < 4; j++) {
        float4 o0 = make_float4(cnt[0][j], cnt[1][j], cnt[2][j], cnt[3][j]);
        float4 o1 = make_float4(cnt[4][j], cnt[5][j], cnt[6][j], cnt[7][j]);
        float* po = out + ((size_t)(b * COUT + m0 + j0 + j)) * 1024 + hw0 + i0;
        *(float4*)po = o0;
        *(float4*)(po + 4) = o1;
    }
}

extern "C" void kernel_launch(void* const* d_in, const int* in_sizes, int n_in,
                              void* d_out, int out_size) {
    const float* inp = (const float*)d_in[0];  // [16,128,32,32]
    const float* wt  = (const float*)d_in[1];  // [256,128,3,3]
    float* out = (float*)d_out;                // [16,256,32,32]

    k_init<<<1, 1>>>();
    k_minmax<<<288, 256>>>(wt);
    k_quant<<<DTOT, 256>>>(wt);
    k_gemm<<<512, 256>>>(inp, out);
}

// round 4
// speedup vs baseline: 2.2031x; 2.2031x over previous
#include <cuda_runtime.h>
#include <cuda_fp16.h>
#include <cstdint>

// Problem constants
#define CIN   128
#define COUT  256
#define DTOT  1152     // 18 chunks * 64
#define RCH   18
#define NPIX  16384

// ---------------- device scratch (no cudaMalloc allowed) ----------------
__device__ __half   g_wqh[COUT * DTOT];  // quantized weight fp16, row-major [m][d]
__device__ int      g_tab[DTOT];         // packed im2col offsets: off | (p<<20)
__device__ unsigned g_kmin, g_kmax;

// ---------------- helpers ----------------
__device__ __forceinline__ unsigned f2key(float f) {
    unsigned u = __float_as_uint(f);
    return (u & 0x80000000u) ? ~u : (u | 0x80000000u);
}
__device__ __forceinline__ float key2f(unsigned k) {
    unsigned u = (k & 0x80000000u) ? (k ^ 0x80000000u) : ~k;
    return __uint_as_float(u);
}
__device__ __forceinline__ uint32_t smem_u32(const void* p) {
    uint32_t a;
    asm("{ .reg .u64 t; cvta.to.shared.u64 t, %1; cvt.u32.u64 %0, t; }" : "=r"(a) : "l"(p));
    return a;
}

#define LDSM4(r, addr)                                                         \
    asm volatile("ldmatrix.sync.aligned.m8n8.x4.shared.b16 {%0,%1,%2,%3},[%4];"\
        : "=r"((r)[0]), "=r"((r)[1]), "=r"((r)[2]), "=r"((r)[3]) : "r"(addr))

#define MMA16816(c, a, b0v, b1v)                                               \
    asm volatile("mma.sync.aligned.m16n8k16.row.col.f32.f16.f16.f32 "          \
        "{%0,%1,%2,%3},{%4,%5,%6,%7},{%8,%9},{%0,%1,%2,%3};"                   \
        : "+f"((c)[0]), "+f"((c)[1]), "+f"((c)[2]), "+f"((c)[3])               \
        : "r"((a)[0]), "r"((a)[1]), "r"((a)[2]), "r"((a)[3]),                  \
          "r"(b0v), "r"(b1v))

// ---------------- prep kernels ----------------
__global__ void k_init() { g_kmin = 0xFFFFFFFFu; g_kmax = 0u; }

// 288 blocks x 256 threads x float4 = 294912 elements exactly
__global__ void k_minmax(const float* __restrict__ w) {
    int idx = (blockIdx.x * 256 + threadIdx.x) * 4;
    float4 v = *(const float4*)(w + idx);
    float lmin = fminf(fminf(v.x, v.y), fminf(v.z, v.w));
    float lmax = fmaxf(fmaxf(v.x, v.y), fmaxf(v.z, v.w));
    unsigned kmin = f2key(lmin), kmax = f2key(lmax);
#pragma unroll
    for (int s = 16; s; s >>= 1) {
        kmin = min(kmin, __shfl_xor_sync(0xffffffffu, kmin, s));
        kmax = max(kmax, __shfl_xor_sync(0xffffffffu, kmax, s));
    }
    __shared__ unsigned smin[8], smax[8];
    int wid = threadIdx.x >> 5;
    if ((threadIdx.x & 31) == 0) { smin[wid] = kmin; smax[wid] = kmax; }
    __syncthreads();
    if (threadIdx.x == 0) {
#pragma unroll
        for (int i = 1; i < 8; i++) { kmin = min(kmin, smin[i]); kmax = max(kmax, smax[i]); }
        atomicMin(&g_kmin, kmin);
        atomicMax(&g_kmax, kmax);
    }
}

// 288 blocks x 1024 threads: quantize w[m][d] -> fp16 (exact small ints), row-major
__global__ void k_quant(const float* __restrict__ w) {
    float wmin = key2f(g_kmin), wmax = key2f(g_kmax);
    float scale = 15.0f / (wmax - wmin + 1e-9f);
    int idx = blockIdx.x * 1024 + threadIdx.x;   // 294912 total
    float q = rintf(w[idx] * scale);
    q = fminf(fmaxf(q, -7.0f), 7.0f);
    g_wqh[idx] = __float2half_rn(q);
    if (idx < DTOT) {
        int c = idx / 9, p = idx - c * 9, di = p / 3, dj = p - di * 3;
        g_tab[idx] = (c * 1024 + di * 32 + dj) | (p << 20);
    }
}

// ---------------- main HMMA kernel ----------------
// Block tile: 128 pixels x 64 channels, 8 warps, warp tile 32x32.
// grid = (16384/128) * (256/64) = 128 * 4 = 512 blocks.
#define XS_LD 72   // halves per row (64 data + 8 pad): 144B stride -> conflict-free ldmatrix

__global__ void __launch_bounds__(256, 2)
k_mma(const float* __restrict__ inp, float* __restrict__ out) {
    __shared__ __half Xh[128 * XS_LD];
    __shared__ __half Xl[128 * XS_LD];
    __shared__ __half Wt[64 * XS_LD];

    const int tid = threadIdx.x, lane = tid & 31, wid = tid >> 5;
    const int bm = blockIdx.x >> 2;       // pixel block (128 pixels)
    const int bn = blockIdx.x & 3;        // channel block (64 channels)
    const int b = bm >> 3;                // image index
    const int hw0 = (bm & 7) << 7;        // pixel offset within image
    const float* inb = inp + (size_t)b * (CIN * 1024);

    // ---- X loader setup: 128 pixels x 2 half-k groups ----
    const int lpix = tid & 127;
    const int lks = tid >> 7;             // 0/1, covers k 0-31 / 32-63
    const int hw = hw0 + lpix, h = hw >> 5, wc = hw & 31;
    const float* xbase = inb + h * 32 + wc - 33;
    int vmask = 0;
#pragma unroll
    for (int di = 0; di < 3; ++di)
#pragma unroll
        for (int dj = 0; dj < 3; ++dj) {
            int hh = h + di - 1, wwp = wc + dj - 1;
            if (hh >= 0 && hh < 32 && wwp >= 0 && wwp < 32)
                vmask |= 1 << (di * 3 + dj);
        }

    // ---- W loader setup: 64 channels x 4 k16 groups ----
    const int lm = tid & 63;
    const int lk16 = tid >> 6;            // 0..3

    // ---- compute setup ----
    const int wm = wid & 3;               // pixel sub-tile (32 rows)
    const int wn = wid >> 2;              // channel sub-tile (32 cols)
    const uint32_t xh_b = smem_u32(Xh), xl_b = smem_u32(Xl), wt_b = smem_u32(Wt);
    const int rA = wm * 32 + (lane & 15), cA = (lane >> 4) * 8;
    uint32_t aAh0 = xh_b + (rA * XS_LD + cA) * 2;
    uint32_t aAh1 = aAh0 + 16 * XS_LD * 2;
    uint32_t aAl0 = xl_b + (rA * XS_LD + cA) * 2;
    uint32_t aAl1 = aAl0 + 16 * XS_LD * 2;
    const int rB = wn * 32 + (lane & 15), cB = (lane >> 4) * 8;
    uint32_t aB0 = wt_b + (rB * XS_LD + cB) * 2;  // n-tiles 0,1
    uint32_t aB1 = aB0 + 16 * XS_LD * 2;          // n-tiles 2,3

    uint32_t cnt[8];
#pragma unroll
    for (int j = 0; j < 8; j++) cnt[j] = 0;

#pragma unroll 1
    for (int c = 0; c < RCH; c++) {
        // ---- stage X (im2col, fp32 -> hi/lo fp16) ----
        const int* tab = g_tab + c * 64 + lks * 32;
        __half* xhrow = Xh + lpix * XS_LD + lks * 32;
        __half* xlrow = Xl + lpix * XS_LD + lks * 32;
#pragma unroll
        for (int i = 0; i < 4; i++) {     // 8 k's per pass
            uint32_t hi4[4], lo4[4];
#pragma unroll
            for (int t = 0; t < 4; t++) {
                int e0 = tab[i * 8 + t * 2], e1 = tab[i * 8 + t * 2 + 1];
                float v0 = ((vmask >> (e0 >> 20)) & 1) ? __ldg(xbase + (e0 & 0xFFFFF)) : 0.0f;
                float v1 = ((vmask >> (e1 >> 20)) & 1) ? __ldg(xbase + (e1 & 0xFFFFF)) : 0.0f;
                __half2 hh = __floats2half2_rn(v0, v1);
                float2 hf = __half22float2(hh);
                __half2 hl = __floats2half2_rn(v0 - hf.x, v1 - hf.y);
                hi4[t] = *reinterpret_cast<uint32_t*>(&hh);
                lo4[t] = *reinterpret_cast<uint32_t*>(&hl);
            }
            *(uint4*)(xhrow + i * 8) = make_uint4(hi4[0], hi4[1], hi4[2], hi4[3]);
            *(uint4*)(xlrow + i * 8) = make_uint4(lo4[0], lo4[1], lo4[2], lo4[3]);
        }
        // ---- stage W ----
        {
            const __half* wg = g_wqh + (size_t)(bn * 64 + lm) * DTOT + c * 64 + lk16 * 16;
            uint4 w0 = *(const uint4*)wg;
            uint4 w1 = *(const uint4*)(wg + 8);
            __half* wrow = Wt + lm * XS_LD + lk16 * 16;
            *(uint4*)wrow = w0;
            *(uint4*)(wrow + 8) = w1;
        }
        __syncthreads();

        float cacc[2][4][4];
#pragma unroll
        for (int mt = 0; mt < 2; mt++)
#pragma unroll
            for (int nt = 0; nt < 4; nt++)
#pragma unroll
                for (int e = 0; e < 4; e++) cacc[mt][nt][e] = 0.0f;

#pragma unroll
        for (int ks = 0; ks < 4; ks++) {
            const uint32_t off = ks * 32;  // 16 halves per k-step
            uint32_t ah0[4], ah1[4], al0[4], al1[4], b0[4], b1[4];
            LDSM4(ah0, aAh0 + off);
            LDSM4(ah1, aAh1 + off);
            LDSM4(al0, aAl0 + off);
            LDSM4(al1, aAl1 + off);
            // B is K-major in smem -> NON-trans ldmatrix matches mma col-B frag
            LDSM4(b0, aB0 + off);
            LDSM4(b1, aB1 + off);
            // n-tile B frags: 0:(b0[0],b0[2]) 1:(b0[1],b0[3]) 2:(b1[0],b1[2]) 3:(b1[1],b1[3])
            MMA16816(cacc[0][0], ah0, b0[0], b0[2]);
            MMA16816(cacc[0][1], ah0, b0[1], b0[3]);
            MMA16816(cacc[0][2], ah0, b1[0], b1[2]);
            MMA16816(cacc[0][3], ah0, b1[1], b1[3]);
            MMA16816(cacc[1][0], ah1, b0[0], b0[2]);
            MMA16816(cacc[1][1], ah1, b0[1], b0[3]);
            MMA16816(cacc[1][2], ah1, b1[0], b1[2]);
            MMA16816(cacc[1][3], ah1, b1[1], b1[3]);
            MMA16816(cacc[0][0], al0, b0[0], b0[2]);
            MMA16816(cacc[0][1], al0, b0[1], b0[3]);
            MMA16816(cacc[0][2], al0, b1[0], b1[2]);
            MMA16816(cacc[0][3], al0, b1[1], b1[3]);
            MMA16816(cacc[1][0], al1, b0[0], b0[2]);
            MMA16816(cacc[1][1], al1, b0[1], b0[3]);
            MMA16816(cacc[1][2], al1, b1[0], b1[2]);
            MMA16816(cacc[1][3], al1, b1[1], b1[3]);
        }
        __syncthreads();

        // threshold (>= 0 -> +1), packed byte counters
#pragma unroll
        for (int mt = 0; mt < 2; mt++)
#pragma unroll
            for (int nt = 0; nt < 4; nt++)
#pragma unroll
                for (int e = 0; e < 4; e++) {
                    int idx = mt * 16 + nt * 4 + e;
                    uint32_t one = (cacc[mt][nt][e] >= 0.0f) ? 1u : 0u;
                    cnt[idx >> 2] += one << ((idx & 3) * 8);
                }
    }

    // ---- write counts ----
    // c-frag: row = g + (e>>1)*8, col = 2t + (e&1)
    {
        const int g = lane >> 2, t = lane & 3;
        float* obase = out + ((size_t)(b * COUT + bn * 64 + wn * 32) << 10) + hw0;
#pragma unroll
        for (int mt = 0; mt < 2; mt++)
#pragma unroll
            for (int e2 = 0; e2 < 2; e2++) {
                int pixl = wm * 32 + mt * 16 + g + e2 * 8;
#pragma unroll
                for (int nt = 0; nt < 4; nt++)
#pragma unroll
                    for (int e1 = 0; e1 < 2; e1++) {
                        int chan = nt * 8 + 2 * t + e1;
                        int idx = mt * 16 + nt * 4 + e2 * 2 + e1;
                        float val = (float)((cnt[idx >> 2] >> ((idx & 3) * 8)) & 0xFF);
                        obase[((size_t)chan << 10) + pixl] = val;
                    }
            }
    }
}

// ---------------- launch ----------------
extern "C" void kernel_launch(void* const* d_in, const int* in_sizes, int n_in,
                              void* d_out, int out_size) {
    const float* inp = (const float*)d_in[0];  // [16,128,32,32]
    const float* wt  = (const float*)d_in[1];  // [256,128,3,3]
    float* out = (float*)d_out;                // [16,256,32,32]

    k_init<<<1, 1>>>();
    k_minmax<<<288, 256>>>(wt);
    k_quant<<<288, 1024>>>(wt);
    k_mma<<<512, 256>>>(inp, out);
}